// round 1
// baseline (speedup 1.0000x reference)
#include <cuda_runtime.h>
#include <cuda_bf16.h>
#include <math.h>

#define BB 2
#define NN 2048
#define EE 64
#define HH 2
#define KK 2
#define FIN 18
#define MAXDEG_ADJ 64
#define MAXDEG_A2 512
#define FULLMASK 0xffffffffu

// ---------------- device scratch (static, no allocation) ----------------
__device__ float g_h[BB*NN*EE];            // node hidden state
__device__ float g_z[HH*BB*NN*EE];         // per-head projected features
__device__ float g_ssrc[HH*BB*NN];
__device__ float g_sdst[HH*BB*NN];
__device__ float g_zmean[HH*BB*EE];
__device__ float g_aggs[BB*NN*KK*EE];
__device__ unsigned short g_nbr_adj[BB*NN*MAXDEG_ADJ];
__device__ unsigned short g_nbr_a2[BB*NN*MAXDEG_A2];
__device__ int g_deg_adj[BB*NN];
__device__ int g_deg_a2[BB*NN];
__device__ unsigned g_adjbit[BB*NN*(NN/32)];
__device__ float g_nw[BB*NN];
__device__ float g_dv[BB*NN];
__device__ float g_enw[BB*NN];
__device__ float g_Z[BB*NN];
__device__ float g_s10[BB*NN];
__device__ float g_gmax[BB];

__device__ __forceinline__ float warpSum(float v){
    #pragma unroll
    for (int o=16;o;o>>=1) v += __shfl_xor_sync(FULLMASK, v, o);
    return v;
}
__device__ __forceinline__ float warpMax(float v){
    #pragma unroll
    for (int o=16;o;o>>=1) v = fmaxf(v, __shfl_xor_sync(FULLMASK, v, o));
    return v;
}
__device__ __forceinline__ float sigmoidf_(float x){ return 1.0f/(1.0f+__expf(-x)); }

// ---------------- zero output ----------------
__global__ void K_zero(float* out){
    if (threadIdx.x < BB) out[threadIdx.x] = 0.0f;
}

// ---------------- encoder: h = tanh(tanh(x@W0+b0)@W1+b1) ----------------
__global__ __launch_bounds__(256) void K_enc(const float* __restrict__ emb,
                                             const float* __restrict__ feat,
                                             const float* __restrict__ W0,
                                             const float* __restrict__ b0,
                                             const float* __restrict__ W1,
                                             const float* __restrict__ b1){
    __shared__ float sW0[FIN*EE];
    __shared__ float sW1[EE*EE];
    __shared__ float sx[4][FIN];
    __shared__ float st[4][EE];
    int tid = threadIdx.x;
    for (int i = tid; i < FIN*EE; i += 256) sW0[i] = W0[i];
    for (int i = tid; i < EE*EE;  i += 256) sW1[i] = W1[i];
    int g = tid >> 6, e = tid & 63;
    int gn = blockIdx.x*4 + g;
    if (e < 16)       sx[g][e]   = emb[gn*16 + e];
    else if (e < 18)  sx[g][e]   = feat[gn*2 + (e-16)];
    __syncthreads();
    float acc = b0[e];
    #pragma unroll
    for (int d=0; d<FIN; d++) acc += sx[g][d]*sW0[d*EE+e];
    st[g][e] = tanhf(acc);
    __syncthreads();
    float acc2 = b1[e];
    #pragma unroll
    for (int d=0; d<EE; d++) acc2 += st[g][d]*sW1[d*EE+e];
    g_h[gn*EE+e] = tanhf(acc2);
}

// ---------------- CSR + bitset build from dense neighborhoods ----------------
__global__ __launch_bounds__(256) void K_build(const float* __restrict__ neigh){
    int lane = threadIdx.x & 31;
    int row = blockIdx.x*8 + (threadIdx.x >> 5);   // 0 .. KK*BB*NN-1
    int k  = row / (BB*NN);
    int bn = row % (BB*NN);
    const float* src = neigh + (size_t)row * NN;
    unsigned short* dst = (k==0) ? (g_nbr_adj + (size_t)bn*MAXDEG_ADJ)
                                 : (g_nbr_a2  + (size_t)bn*MAXDEG_A2);
    int cap = (k==0) ? MAXDEG_ADJ : MAXDEG_A2;
    int deg = 0;
    #pragma unroll 4
    for (int c=0; c<NN/32; c++){
        int j = c*32 + lane;
        float v = src[j];
        bool p = v > 0.0f;
        unsigned bal = __ballot_sync(FULLMASK, p);
        if (k==0 && lane==0) g_adjbit[(size_t)bn*(NN/32) + c] = bal;
        int pre = __popc(bal & ((1u<<lane)-1u));
        if (p){ int pos = deg + pre; if (pos < cap) dst[pos] = (unsigned short)j; }
        deg += __popc(bal);
    }
    if (lane==0){
        if (deg > cap) deg = cap;
        if (k==0) g_deg_adj[bn] = deg; else g_deg_a2[bn] = deg;
    }
}

// ---------------- per-head projection z + attention logits ----------------
__global__ __launch_bounds__(256) void K_z(const float* __restrict__ attn_W,
                                           const float* __restrict__ a_src,
                                           const float* __restrict__ a_dst){
    int h = blockIdx.y;
    __shared__ float sW[EE*EE];
    __shared__ float sh[4][EE];
    __shared__ float sp[8][2];
    int tid = threadIdx.x;
    const float* W = attn_W + h*EE*EE;
    for (int i=tid;i<EE*EE;i+=256) sW[i] = W[i];
    int g = tid >> 6, e = tid & 63;
    int gn = blockIdx.x*4 + g;
    sh[g][e] = g_h[gn*EE+e];
    __syncthreads();
    float acc = 0.f;
    #pragma unroll
    for (int d=0; d<EE; d++) acc += sh[g][d]*sW[d*EE+e];
    g_z[((size_t)h*BB*NN + gn)*EE + e] = acc;
    float p = acc * a_src[h*EE+e];
    float q = acc * a_dst[h*EE+e];
    p = warpSum(p); q = warpSum(q);
    int w = tid >> 5, lane = tid & 31;
    if (lane==0){ sp[w][0] = p; sp[w][1] = q; }
    __syncthreads();
    if (e == 0){
        g_ssrc[h*BB*NN + gn] = sp[2*g][0] + sp[2*g+1][0];
        g_sdst[h*BB*NN + gn] = sp[2*g][1] + sp[2*g+1][1];
    }
}

// ---------------- z mean over nodes (empty-neighborhood fallback) --------
__global__ __launch_bounds__(256) void K_zmean(){
    int hb = blockIdx.x;           // h*BB + b
    __shared__ float sp[4][EE];
    int part = threadIdx.x >> 6, e = threadIdx.x & 63;
    float s = 0.f;
    for (int n = part; n < NN; n += 4)
        s += g_z[((size_t)hb*NN + n)*EE + e];
    sp[part][e] = s;
    __syncthreads();
    if (threadIdx.x < EE){
        float t = sp[0][threadIdx.x]+sp[1][threadIdx.x]+sp[2][threadIdx.x]+sp[3][threadIdx.x];
        g_zmean[hb*EE + threadIdx.x] = t / (float)NN;
    }
}

// ---------------- neighborhood attention aggregation ----------------
__global__ __launch_bounds__(256) void K_agg(){
    int bn = blockIdx.x;         // b*NN+n
    int k  = blockIdx.y;
    int b  = bn / NN;
    int tid = threadIdx.x, w = tid>>5, lane = tid&31;

    __shared__ float sc0[MAXDEG_A2];
    __shared__ float sc1[MAXDEG_A2];
    __shared__ unsigned short sidx[MAXDEG_A2];
    __shared__ float srA[8], srB[8];
    __shared__ float sM[4];           // M0,M1,S0,S1
    __shared__ float sacc0[4][EE], sacc1[4][EE];

    int deg = (k==0) ? g_deg_adj[bn] : g_deg_a2[bn];
    const unsigned short* list = (k==0) ? (g_nbr_adj + (size_t)bn*MAXDEG_ADJ)
                                        : (g_nbr_a2  + (size_t)bn*MAXDEG_A2);
    if (deg == 0){
        if (tid < EE){
            float v = 0.5f*(g_zmean[(0*BB+b)*EE+tid] + g_zmean[(1*BB+b)*EE+tid]);
            g_aggs[((size_t)bn*KK + k)*EE + tid] = tanhf(v);
        }
        return;
    }
    float ssrc0 = g_ssrc[0*BB*NN + bn];
    float ssrc1 = g_ssrc[1*BB*NN + bn];
    const float* sd0 = g_sdst + 0*BB*NN + b*NN;
    const float* sd1 = g_sdst + 1*BB*NN + b*NN;

    // pass 1: scores + max
    float m0 = -1e30f, m1 = -1e30f;
    for (int t = tid; t < deg; t += 256){
        int j = list[t]; sidx[t] = (unsigned short)j;
        float x0 = tanhf(ssrc0 + sd0[j]);
        float x1 = tanhf(ssrc1 + sd1[j]);
        sc0[t] = x0; sc1[t] = x1;
        m0 = fmaxf(m0, x0); m1 = fmaxf(m1, x1);
    }
    m0 = warpMax(m0); m1 = warpMax(m1);
    if (lane==0){ srA[w]=m0; srB[w]=m1; }
    __syncthreads();
    if (tid==0){
        float a=srA[0], c=srB[0];
        for(int i=1;i<8;i++){ a=fmaxf(a,srA[i]); c=fmaxf(c,srB[i]); }
        sM[0]=a; sM[1]=c;
    }
    __syncthreads();
    float M0 = sM[0], M1 = sM[1];

    // pass 2: exp + sum
    float s0 = 0.f, s1 = 0.f;
    for (int t = tid; t < deg; t += 256){
        float e0 = __expf(sc0[t]-M0);
        float e1 = __expf(sc1[t]-M1);
        sc0[t] = e0; sc1[t] = e1;
        s0 += e0; s1 += e1;
    }
    s0 = warpSum(s0); s1 = warpSum(s1);
    if (lane==0){ srA[w]=s0; srB[w]=s1; }
    __syncthreads();
    if (tid==0){
        float a=0, c=0; for(int i=0;i<8;i++){ a+=srA[i]; c+=srB[i]; }
        sM[2]=a; sM[3]=c;
    }
    __syncthreads();
    float inv0 = 1.0f/sM[2], inv1 = 1.0f/sM[3];

    // pass 3: weighted sum of z rows
    int g = tid >> 6, e = tid & 63;
    float a0 = 0.f, a1 = 0.f;
    const float* zb0 = g_z + ((size_t)0*BB + b)*NN*EE;
    const float* zb1 = g_z + ((size_t)1*BB + b)*NN*EE;
    for (int t = g; t < deg; t += 4){
        int j = sidx[t];
        a0 += sc0[t]*zb0[(size_t)j*EE + e];
        a1 += sc1[t]*zb1[(size_t)j*EE + e];
    }
    sacc0[g][e] = a0; sacc1[g][e] = a1;
    __syncthreads();
    if (tid < EE){
        float r0 = sacc0[0][tid]+sacc0[1][tid]+sacc0[2][tid]+sacc0[3][tid];
        float r1 = sacc1[0][tid]+sacc1[1][tid]+sacc1[2][tid]+sacc1[3][tid];
        float v = 0.5f*(r0*inv0 + r1*inv1);
        g_aggs[((size_t)bn*KK + k)*EE + tid] = tanhf(v);
    }
}

// ---------------- combine neighborhoods + GRU update (fused) -------------
__global__ __launch_bounds__(256) void K_gru(const float* __restrict__ nbr_q,
                                             const float* __restrict__ gru_W,
                                             const float* __restrict__ gru_U,
                                             const float* __restrict__ gru_b){
    extern __shared__ float dyn[];
    float* sW = dyn;              // 64*192
    float* sU = dyn + EE*192;     // 64*192
    __shared__ float snxt[8][EE];
    __shared__ float shh [8][EE];
    __shared__ float srh [8][EE];
    int tid = threadIdx.x;
    for (int i=tid;i<EE*192;i+=256){ sW[i]=gru_W[i]; sU[i]=gru_U[i]; }
    __syncthreads();
    int w = tid>>5, lane = tid&31;
    int e1 = lane, e2 = lane+32;
    #pragma unroll
    for (int rep=0; rep<2; rep++){
        int gn = blockIdx.x*16 + w + rep*8;
        const float* ag = g_aggs + (size_t)gn*KK*EE;
        float a0_1 = ag[e1],      a0_2 = ag[e2];
        float a1_1 = ag[EE+e1],   a1_2 = ag[EE+e2];
        float d0 = warpSum(a0_1*nbr_q[e1] + a0_2*nbr_q[e2]);
        float d1 = warpSum(a1_1*nbr_q[e1] + a1_2*nbr_q[e2]);
        float t0 = tanhf(d0), t1 = tanhf(d1);
        float mx = fmaxf(t0,t1);
        float ex0 = __expf(t0-mx), ex1 = __expf(t1-mx);
        float inv = 1.0f/(ex0+ex1);
        float c0 = ex0*inv, c1 = ex1*inv;
        float nx1 = c0*a0_1 + c1*a1_1;
        float nx2 = c0*a0_2 + c1*a1_2;
        float h1 = g_h[(size_t)gn*EE+e1], h2 = g_h[(size_t)gn*EE+e2];
        snxt[w][e1]=nx1; snxt[w][e2]=nx2;
        shh [w][e1]=h1;  shh [w][e2]=h2;
        __syncwarp();
        float az1 = gru_b[e1],    az2 = gru_b[e2];
        float ar1 = gru_b[64+e1], ar2 = gru_b[64+e2];
        #pragma unroll
        for (int d=0; d<EE; d++){
            float nx = snxt[w][d], hv = shh[w][d];
            az1 += nx*sW[d*192+e1]    + hv*sU[d*192+e1];
            az2 += nx*sW[d*192+e2]    + hv*sU[d*192+e2];
            ar1 += nx*sW[d*192+64+e1] + hv*sU[d*192+64+e1];
            ar2 += nx*sW[d*192+64+e2] + hv*sU[d*192+64+e2];
        }
        float zg1 = sigmoidf_(az1), zg2 = sigmoidf_(az2);
        float r1  = sigmoidf_(ar1), r2  = sigmoidf_(ar2);
        srh[w][e1] = r1*h1; srh[w][e2] = r2*h2;
        __syncwarp();
        float at1 = gru_b[128+e1], at2 = gru_b[128+e2];
        #pragma unroll
        for (int d=0; d<EE; d++){
            float nx = snxt[w][d], rh = srh[w][d];
            at1 += nx*sW[d*192+128+e1] + rh*sU[d*192+128+e1];
            at2 += nx*sW[d*192+128+e2] + rh*sU[d*192+128+e2];
        }
        float ht1 = tanhf(at1), ht2 = tanhf(at2);
        g_h[(size_t)gn*EE+e1] = (1.0f-zg1)*h1 + zg1*ht1;
        g_h[(size_t)gn*EE+e2] = (1.0f-zg2)*h2 + zg2*ht2;
    }
}

// ---------------- decoder + dual heads (node scalars) ----------------
__global__ __launch_bounds__(256) void K_dec_dual(const float* __restrict__ dW0, const float* __restrict__ db0,
                                                  const float* __restrict__ dW1, const float* __restrict__ db1,
                                                  const float* __restrict__ uW0, const float* __restrict__ ub0,
                                                  const float* __restrict__ uW1, const float* __restrict__ ub1){
    __shared__ float sWd[EE*EE];
    __shared__ float sWu[EE*EE];
    __shared__ float shh[8][EE];
    int tid = threadIdx.x;
    for (int i=tid;i<EE*EE;i+=256){ sWd[i]=dW0[i]; sWu[i]=uW0[i]; }
    __syncthreads();
    int w = tid>>5, lane = tid&31;
    int e1 = lane, e2 = lane+32;
    #pragma unroll
    for (int rep=0; rep<2; rep++){
        int gn = blockIdx.x*16 + w + rep*8;
        float h1 = g_h[(size_t)gn*EE+e1], h2 = g_h[(size_t)gn*EE+e2];
        shh[w][e1]=h1; shh[w][e2]=h2;
        __syncwarp();
        // decoder
        float t1 = db0[e1], t2 = db0[e2];
        #pragma unroll
        for (int d=0; d<EE; d++){ float hv=shh[w][d]; t1 += hv*sWd[d*EE+e1]; t2 += hv*sWd[d*EE+e2]; }
        t1 = tanhf(t1); t2 = tanhf(t2);
        float p = warpSum(t1*dW1[e1] + t2*dW1[e2]);
        if (lane==0) g_nw[gn] = p + db1[0];
        // dual
        float u1 = ub0[e1], u2 = ub0[e2];
        #pragma unroll
        for (int d=0; d<EE; d++){ float hv=shh[w][d]; u1 += hv*sWu[d*EE+e1]; u2 += hv*sWu[d*EE+e2]; }
        u1 = tanhf(u1); u2 = tanhf(u2);
        float q = warpSum(u1*uW1[e1] + u2*uW1[e2]);
        if (lane==0) g_dv[gn] = q + ub1[0];
        __syncwarp();
    }
}

// ---------------- global max of nw per batch ----------------
__global__ __launch_bounds__(256) void K_gmax(){
    int b = blockIdx.x;
    __shared__ float sr[8];
    float m = -1e30f;
    for (int n = threadIdx.x; n < NN; n += 256) m = fmaxf(m, g_nw[b*NN+n]);
    m = warpMax(m);
    if ((threadIdx.x&31)==0) sr[threadIdx.x>>5] = m;
    __syncthreads();
    if (threadIdx.x==0){
        float t = sr[0]; for(int i=1;i<8;i++) t=fmaxf(t,sr[i]);
        g_gmax[b] = t;
    }
}

// ---------------- softmax denominators + exp(nw) ----------------
__global__ __launch_bounds__(256) void K_prop(){
    int w = threadIdx.x>>5, lane = threadIdx.x&31;
    int gn = blockIdx.x*8 + w;
    int b = gn / NN;
    float gm = g_gmax[b];
    int deg = g_deg_adj[gn];
    const unsigned short* list = g_nbr_adj + (size_t)gn*MAXDEG_ADJ;
    float s = 0.f;
    for (int t=lane; t<deg; t+=32) s += __expf(g_nw[b*NN + list[t]] - gm);
    s = warpSum(s);
    if (lane==0){
        g_Z[gn] = (deg>0) ? s : 1.0f;
        g_enw[gn] = __expf(g_nw[gn] - gm);
    }
}

// ---------------- fused 10-iteration MCF on node vectors ----------------
__global__ __launch_bounds__(1024) void K_flow(const float* __restrict__ demands){
    int b = blockIdx.x;
    __shared__ float s[NN];
    __shared__ float acc[NN];
    int n1 = threadIdx.x, n2 = threadIdx.x + 1024;
    int gn1 = b*NN+n1, gn2 = b*NN+n2;
    float invZ1 = 1.0f/g_Z[gn1], invZ2 = 1.0f/g_Z[gn2];
    float d1 = demands[gn1], d2 = demands[gn2];
    float e1 = g_enw[gn1],  e2 = g_enw[gn2];
    int dg1 = g_deg_adj[gn1], dg2 = g_deg_adj[gn2];
    const unsigned short* l1 = g_nbr_adj + (size_t)gn1*MAXDEG_ADJ;
    const unsigned short* l2 = g_nbr_adj + (size_t)gn2*MAXDEG_ADJ;
    s[n1]=0.f; s[n2]=0.f;
    __syncthreads();
    for (int it=0; it<10; it++){
        acc[n1]=0.f; acc[n2]=0.f;
        __syncthreads();
        float u1 = s[n1]*invZ1;
        for (int t=0; t<dg1; t++) atomicAdd(&acc[l1[t]], u1);
        float u2 = s[n2]*invZ2;
        for (int t=0; t<dg2; t++) atomicAdd(&acc[l2[t]], u2);
        __syncthreads();
        s[n1] = fmaxf(e1*acc[n1] - d1, 0.f);
        s[n2] = fmaxf(e2*acc[n2] - d2, 0.f);
        __syncthreads();
    }
    g_s10[gn1] = s[n1];
    g_s10[gn2] = s[n2];
}

// ---------------- flow cost + dual iterations + final reduction ----------
__global__ __launch_bounds__(256) void K_final(const float* __restrict__ demands,
                                               float* __restrict__ out){
    int b = blockIdx.y;
    int tid = threadIdx.x, w = tid>>5, lane = tid&31;
    float acc = 0.f;
    for (int idx = w; idx < 64; idx += 8){
        int n = blockIdx.x*64 + idx;
        int gn = b*NN+n;
        int deg = g_deg_adj[gn];
        const unsigned short* list = g_nbr_adj + (size_t)gn*MAXDEG_ADJ;
        float si = g_s10[gn];
        float invZi = 1.0f/g_Z[gn];
        float dvi = g_dv[gn];
        float enwi = g_enw[gn];
        if (lane==0) acc += dvi * demands[gn];   // dual_demand (added to output)
        for (int t=lane; t<deg; t+=32){
            int j = list[t];
            int gj = b*NN+j;
            float f = g_enw[gj]*invZi*si;
            unsigned word = g_adjbit[(size_t)gj*(NN/32) + (n>>5)];
            float ft = 0.f;
            if ((word >> (n&31)) & 1u) ft = enwi * (g_s10[gj]/g_Z[gj]);
            float fp = f - fminf(f, ft);
            acc += fp*fp;
            float dd = dvi - g_dv[gj];
            float y = 0.f, m = 0.f;
            #pragma unroll
            for (int q=0; q<10; q++){
                float gg = 2.0f*y - dd;
                m = 0.9f*m + gg;
                y = fmaxf(y - 0.1f*m, 0.f);
            }
            acc -= (y*y - dd*y);   // minus dual edge term
        }
    }
    acc = warpSum(acc);
    __shared__ float sr[8];
    if (lane==0) sr[w] = acc;
    __syncthreads();
    if (tid==0){
        float t = 0.f; for (int i=0;i<8;i++) t += sr[i];
        atomicAdd(&out[b], t);
    }
}

// ---------------- launch ----------------
extern "C" void kernel_launch(void* const* d_in, const int* in_sizes, int n_in,
                              void* d_out, int out_size){
    const float* feat    = (const float*)d_in[0];
    const float* emb     = (const float*)d_in[1];
    const float* demands = (const float*)d_in[2];
    const float* neigh   = (const float*)d_in[4];
    const float* enc_W0  = (const float*)d_in[5];
    const float* enc_b0  = (const float*)d_in[6];
    const float* enc_W1  = (const float*)d_in[7];
    const float* enc_b1  = (const float*)d_in[8];
    const float* attn_W  = (const float*)d_in[9];
    const float* a_src   = (const float*)d_in[10];
    const float* a_dst   = (const float*)d_in[11];
    const float* nbr_q   = (const float*)d_in[12];
    const float* gru_W   = (const float*)d_in[13];
    const float* gru_U   = (const float*)d_in[14];
    const float* gru_b   = (const float*)d_in[15];
    const float* dec_W0  = (const float*)d_in[16];
    const float* dec_b0  = (const float*)d_in[17];
    const float* dec_W1  = (const float*)d_in[18];
    const float* dec_b1  = (const float*)d_in[19];
    const float* dual_W0 = (const float*)d_in[20];
    const float* dual_b0 = (const float*)d_in[21];
    const float* dual_W1 = (const float*)d_in[22];
    const float* dual_b1 = (const float*)d_in[23];
    float* out = (float*)d_out;

    cudaFuncSetAttribute(K_gru, cudaFuncAttributeMaxDynamicSharedMemorySize, 2*EE*192*4);

    K_zero<<<1,32>>>(out);
    K_enc<<<BB*NN/4,256>>>(emb, feat, enc_W0, enc_b0, enc_W1, enc_b1);
    K_build<<<KK*BB*NN/8,256>>>(neigh);
    for (int l=0;l<2;l++){
        K_z<<<dim3(BB*NN/4,HH),256>>>(attn_W, a_src, a_dst);
        K_zmean<<<HH*BB,256>>>();
        K_agg<<<dim3(BB*NN,KK),256>>>();
        K_gru<<<BB*NN/16,256, 2*EE*192*4>>>(nbr_q, gru_W, gru_U, gru_b);
    }
    K_dec_dual<<<BB*NN/16,256>>>(dec_W0,dec_b0,dec_W1,dec_b1,dual_W0,dual_b0,dual_W1,dual_b1);
    K_gmax<<<BB,256>>>();
    K_prop<<<BB*NN/8,256>>>();
    K_flow<<<BB,1024>>>(demands);
    K_final<<<dim3(NN/64,BB),256>>>(demands, out);
}

// round 3
// speedup vs baseline: 1.1194x; 1.1194x over previous
#include <cuda_runtime.h>
#include <cuda_bf16.h>
#include <math.h>

#define BB 2
#define NN 2048
#define EE 64
#define HH 2
#define KK 2
#define FIN 18
#define MAXDEG_ADJ 64
#define MAXDEG_A2 512
#define MAXDEG_IN 64
#define FULLMASK 0xffffffffu

// ---------------- device scratch (static, no allocation) ----------------
__device__ float g_h[BB*NN*EE];            // node hidden state
__device__ float g_zp[BB*NN*2*EE];         // packed per-node [head0 e0..63 | head1 e0..63]
__device__ float g_ssrc[HH*BB*NN];
__device__ float g_sdst[HH*BB*NN];
__device__ float g_zmean[HH*BB*EE];
__device__ float g_aggs[BB*NN*KK*EE];
__device__ unsigned short g_nbr_adj[BB*NN*MAXDEG_ADJ];
__device__ unsigned short g_nbr_a2[BB*NN*MAXDEG_A2];
__device__ unsigned short g_rin[BB*NN*MAXDEG_IN];
__device__ int g_deg_adj[BB*NN];
__device__ int g_deg_a2[BB*NN];
__device__ int g_rdeg[BB*NN];
__device__ unsigned g_adjbit[BB*NN*(NN/32)];
__device__ float g_nw[BB*NN];
__device__ float g_dv[BB*NN];
__device__ float g_enw[BB*NN];
__device__ float g_Z[BB*NN];
__device__ float g_s10[BB*NN];
__device__ float g_gmax[BB];

__device__ __forceinline__ float warpSum(float v){
    #pragma unroll
    for (int o=16;o;o>>=1) v += __shfl_xor_sync(FULLMASK, v, o);
    return v;
}
__device__ __forceinline__ float warpMax(float v){
    #pragma unroll
    for (int o=16;o;o>>=1) v = fmaxf(v, __shfl_xor_sync(FULLMASK, v, o));
    return v;
}
__device__ __forceinline__ float sigmoidf_(float x){ return 1.0f/(1.0f+__expf(-x)); }

// ---------------- zero output + reverse-degree counters ----------------
__global__ void K_zero(float* out){
    int idx = blockIdx.x*256 + threadIdx.x;
    if (idx < BB) out[idx] = 0.0f;
    if (idx < BB*NN) g_rdeg[idx] = 0;
}

// ---------------- encoder: h = tanh(tanh(x@W0+b0)@W1+b1) ----------------
__global__ __launch_bounds__(256) void K_enc(const float* __restrict__ emb,
                                             const float* __restrict__ feat,
                                             const float* __restrict__ W0,
                                             const float* __restrict__ b0,
                                             const float* __restrict__ W1,
                                             const float* __restrict__ b1){
    __shared__ float sW0[FIN*EE];
    __shared__ float sW1[EE*EE];
    __shared__ float sx[4][FIN];
    __shared__ float st[4][EE];
    int tid = threadIdx.x;
    for (int i = tid; i < FIN*EE; i += 256) sW0[i] = W0[i];
    for (int i = tid; i < EE*EE;  i += 256) sW1[i] = W1[i];
    int g = tid >> 6, e = tid & 63;
    int gn = blockIdx.x*4 + g;
    if (e < 16)       sx[g][e]   = emb[gn*16 + e];
    else if (e < 18)  sx[g][e]   = feat[gn*2 + (e-16)];
    __syncthreads();
    float acc = b0[e];
    #pragma unroll
    for (int d=0; d<FIN; d++) acc += sx[g][d]*sW0[d*EE+e];
    st[g][e] = tanhf(acc);
    __syncthreads();
    float acc2 = b1[e];
    #pragma unroll
    for (int d=0; d<EE; d++) acc2 += st[g][d]*sW1[d*EE+e];
    g_h[gn*EE+e] = tanhf(acc2);
}

// ---------------- CSR + bitset + reverse-CSR build ----------------
__global__ __launch_bounds__(256) void K_build(const float* __restrict__ neigh){
    int lane = threadIdx.x & 31;
    int row = blockIdx.x*8 + (threadIdx.x >> 5);   // 0 .. KK*BB*NN-1
    int k  = row / (BB*NN);
    int bn = row % (BB*NN);
    int b_ = bn / NN, i_ = bn % NN;
    const float* src = neigh + (size_t)row * NN;
    unsigned short* dst = (k==0) ? (g_nbr_adj + (size_t)bn*MAXDEG_ADJ)
                                 : (g_nbr_a2  + (size_t)bn*MAXDEG_A2);
    int cap = (k==0) ? MAXDEG_ADJ : MAXDEG_A2;
    int deg = 0;
    #pragma unroll 4
    for (int c=0; c<NN/32; c++){
        int j = c*32 + lane;
        float v = src[j];
        bool p = v > 0.0f;
        unsigned bal = __ballot_sync(FULLMASK, p);
        if (k==0 && lane==0) g_adjbit[(size_t)bn*(NN/32) + c] = bal;
        int pre = __popc(bal & ((1u<<lane)-1u));
        if (p){
            int pos = deg + pre;
            if (pos < cap) dst[pos] = (unsigned short)j;
            if (k==0){
                int rp = atomicAdd(&g_rdeg[b_*NN + j], 1);
                if (rp < MAXDEG_IN) g_rin[(size_t)(b_*NN+j)*MAXDEG_IN + rp] = (unsigned short)i_;
            }
        }
        deg += __popc(bal);
    }
    if (lane==0){
        if (deg > cap) deg = cap;
        if (k==0) g_deg_adj[bn] = deg; else g_deg_a2[bn] = deg;
    }
}

// ---------------- per-head projection z + attention logits ----------------
// 64 nodes per block, 256 threads; thread computes 4 e's x 4 nodes (16 accs)
__global__ __launch_bounds__(256) void K_z(const float* __restrict__ attn_W,
                                           const float* __restrict__ a_src,
                                           const float* __restrict__ a_dst){
    int h = blockIdx.y;
    __shared__ __align__(16) float sW[EE*EE];     // [d][e]
    __shared__ __align__(16) float sh[64][EE];
    __shared__ __align__(16) float sz[64][EE];
    int tid = threadIdx.x;
    const float* W = attn_W + h*EE*EE;
    for (int i=tid;i<EE*EE;i+=256) sW[i] = W[i];
    int gn0 = blockIdx.x*64;
    for (int i=tid;i<64*EE;i+=256) sh[i>>6][i&63] = g_h[(size_t)gn0*EE + i];
    __syncthreads();
    int eg = tid & 15;          // e-group: elements eg*4..eg*4+3
    int ng = tid >> 4;          // node group: nodes ng*4..ng*4+3
    float4 acc0 = {0,0,0,0}, acc1 = {0,0,0,0}, acc2 = {0,0,0,0}, acc3 = {0,0,0,0};
    const float4* sW4 = (const float4*)sW;
    #pragma unroll 4
    for (int d=0; d<EE; d++){
        float4 wv = sW4[d*16 + eg];
        float h0 = sh[ng*4+0][d];
        float h1 = sh[ng*4+1][d];
        float h2 = sh[ng*4+2][d];
        float h3 = sh[ng*4+3][d];
        acc0.x += h0*wv.x; acc0.y += h0*wv.y; acc0.z += h0*wv.z; acc0.w += h0*wv.w;
        acc1.x += h1*wv.x; acc1.y += h1*wv.y; acc1.z += h1*wv.z; acc1.w += h1*wv.w;
        acc2.x += h2*wv.x; acc2.y += h2*wv.y; acc2.z += h2*wv.z; acc2.w += h2*wv.w;
        acc3.x += h3*wv.x; acc3.y += h3*wv.y; acc3.z += h3*wv.z; acc3.w += h3*wv.w;
    }
    float4* zout;
    #define WRITEZ(i, a) { int n = ng*4+i; \
        *(float4*)(&sz[n][eg*4]) = a; \
        zout = (float4*)(g_zp + ((size_t)(gn0+n))*2*EE + h*EE + eg*4); *zout = a; }
    WRITEZ(0, acc0); WRITEZ(1, acc1); WRITEZ(2, acc2); WRITEZ(3, acc3);
    #undef WRITEZ
    __syncthreads();
    int w = tid>>5, lane = tid&31;
    float as1 = a_src[h*EE+lane], as2 = a_src[h*EE+lane+32];
    float ad1 = a_dst[h*EE+lane], ad2 = a_dst[h*EE+lane+32];
    for (int r=0; r<8; r++){
        int n = w*8 + r;
        float z1 = sz[n][lane], z2 = sz[n][lane+32];
        float p = warpSum(z1*as1 + z2*as2);
        float q = warpSum(z1*ad1 + z2*ad2);
        if (lane==0){
            g_ssrc[h*BB*NN + gn0 + n] = p;
            g_sdst[h*BB*NN + gn0 + n] = q;
        }
    }
}

// ---------------- z mean over nodes (empty-neighborhood fallback) --------
__global__ __launch_bounds__(256) void K_zmean(){
    int hb = blockIdx.x;           // h*BB + b
    int h = hb / BB, b = hb % BB;
    __shared__ float sp[4][EE];
    int part = threadIdx.x >> 6, e = threadIdx.x & 63;
    float s = 0.f;
    for (int n = part; n < NN; n += 4)
        s += g_zp[((size_t)(b*NN+n))*2*EE + h*EE + e];
    sp[part][e] = s;
    __syncthreads();
    if (threadIdx.x < EE){
        float t = sp[0][threadIdx.x]+sp[1][threadIdx.x]+sp[2][threadIdx.x]+sp[3][threadIdx.x];
        g_zmean[hb*EE + threadIdx.x] = t / (float)NN;
    }
}

// ---------------- neighborhood attention aggregation (single fused pass) ----
// scores are tanh-bounded => exp never overflows => no max pass needed.
// One warp gathers one neighbor's packed 512B z-row as 32 x float4.
__global__ __launch_bounds__(256) void K_agg(){
    int bn = blockIdx.x;         // b*NN+n
    int k  = blockIdx.y;
    int b  = bn / NN;
    int tid = threadIdx.x, w = tid>>5, lane = tid&31;

    __shared__ float sacc[8][128];
    __shared__ float sw0[8], sw1[8];

    int deg = (k==0) ? g_deg_adj[bn] : g_deg_a2[bn];
    const unsigned short* list = (k==0) ? (g_nbr_adj + (size_t)bn*MAXDEG_ADJ)
                                        : (g_nbr_a2  + (size_t)bn*MAXDEG_A2);
    if (deg == 0){
        if (tid < EE){
            float v = 0.5f*(g_zmean[(0*BB+b)*EE+tid] + g_zmean[(1*BB+b)*EE+tid]);
            g_aggs[((size_t)bn*KK + k)*EE + tid] = tanhf(v);
        }
        return;
    }
    float ssrc0 = g_ssrc[0*BB*NN + bn];
    float ssrc1 = g_ssrc[1*BB*NN + bn];
    const float* sd0 = g_sdst + 0*BB*NN + b*NN;
    const float* sd1 = g_sdst + 1*BB*NN + b*NN;
    const float* zb  = g_zp + (size_t)b*NN*2*EE;

    float a0=0.f, a1=0.f, a2=0.f, a3=0.f;   // 4 elements of packed 128-vector
    float s0=0.f, s1=0.f;                   // weight sums per head
    for (int base = w*32; base < deg; base += 256){
        int tl = base + lane;
        int jl = 0; float w0l = 0.f, w1l = 0.f;
        if (tl < deg){
            jl = list[tl];
            w0l = __expf(tanhf(ssrc0 + sd0[jl]));
            w1l = __expf(tanhf(ssrc1 + sd1[jl]));
        }
        s0 += w0l; s1 += w1l;
        int cnt = deg - base; if (cnt > 32) cnt = 32;
        for (int i=0; i<cnt; i++){
            int j    = __shfl_sync(FULLMASK, jl,  i);
            float wa = __shfl_sync(FULLMASK, w0l, i);
            float wb = __shfl_sync(FULLMASK, w1l, i);
            float wt = (lane < 16) ? wa : wb;
            float4 v = *(const float4*)(zb + (size_t)j*2*EE + lane*4);
            a0 += wt*v.x; a1 += wt*v.y; a2 += wt*v.z; a3 += wt*v.w;
        }
    }
    s0 = warpSum(s0); s1 = warpSum(s1);
    if (lane==0){ sw0[w]=s0; sw1[w]=s1; }
    sacc[w][lane*4+0]=a0; sacc[w][lane*4+1]=a1;
    sacc[w][lane*4+2]=a2; sacc[w][lane*4+3]=a3;
    __syncthreads();
    if (tid < EE){
        float r0=0.f, r1=0.f, S0=0.f, S1=0.f;
        #pragma unroll
        for (int ww=0; ww<8; ww++){
            r0 += sacc[ww][tid];
            r1 += sacc[ww][64+tid];
            S0 += sw0[ww]; S1 += sw1[ww];
        }
        float v = 0.5f*(r0/S0 + r1/S1);
        g_aggs[((size_t)bn*KK + k)*EE + tid] = tanhf(v);
    }
}

// ---------------- combine neighborhoods + GRU update (fused) -------------
__global__ __launch_bounds__(256) void K_gru(const float* __restrict__ nbr_q,
                                             const float* __restrict__ gru_W,
                                             const float* __restrict__ gru_U,
                                             const float* __restrict__ gru_b){
    extern __shared__ float dyn[];
    float* sW = dyn;              // 64*192
    float* sU = dyn + EE*192;     // 64*192
    __shared__ float snxt[8][EE];
    __shared__ float shh [8][EE];
    __shared__ float srh [8][EE];
    int tid = threadIdx.x;
    for (int i=tid;i<EE*192;i+=256){ sW[i]=gru_W[i]; sU[i]=gru_U[i]; }
    __syncthreads();
    int w = tid>>5, lane = tid&31;
    int e1 = lane, e2 = lane+32;
    #pragma unroll
    for (int rep=0; rep<2; rep++){
        int gn = blockIdx.x*16 + w + rep*8;
        const float* ag = g_aggs + (size_t)gn*KK*EE;
        float a0_1 = ag[e1],      a0_2 = ag[e2];
        float a1_1 = ag[EE+e1],   a1_2 = ag[EE+e2];
        float d0 = warpSum(a0_1*nbr_q[e1] + a0_2*nbr_q[e2]);
        float d1 = warpSum(a1_1*nbr_q[e1] + a1_2*nbr_q[e2]);
        float t0 = tanhf(d0), t1 = tanhf(d1);
        float mx = fmaxf(t0,t1);
        float ex0 = __expf(t0-mx), ex1 = __expf(t1-mx);
        float inv = 1.0f/(ex0+ex1);
        float c0 = ex0*inv, c1 = ex1*inv;
        float nx1 = c0*a0_1 + c1*a1_1;
        float nx2 = c0*a0_2 + c1*a1_2;
        float h1 = g_h[(size_t)gn*EE+e1], h2 = g_h[(size_t)gn*EE+e2];
        snxt[w][e1]=nx1; snxt[w][e2]=nx2;
        shh [w][e1]=h1;  shh [w][e2]=h2;
        __syncwarp();
        float az1 = gru_b[e1],    az2 = gru_b[e2];
        float ar1 = gru_b[64+e1], ar2 = gru_b[64+e2];
        #pragma unroll
        for (int d=0; d<EE; d++){
            float nx = snxt[w][d], hv = shh[w][d];
            az1 += nx*sW[d*192+e1]    + hv*sU[d*192+e1];
            az2 += nx*sW[d*192+e2]    + hv*sU[d*192+e2];
            ar1 += nx*sW[d*192+64+e1] + hv*sU[d*192+64+e1];
            ar2 += nx*sW[d*192+64+e2] + hv*sU[d*192+64+e2];
        }
        float zg1 = sigmoidf_(az1), zg2 = sigmoidf_(az2);
        float r1  = sigmoidf_(ar1), r2  = sigmoidf_(ar2);
        srh[w][e1] = r1*h1; srh[w][e2] = r2*h2;
        __syncwarp();
        float at1 = gru_b[128+e1], at2 = gru_b[128+e2];
        #pragma unroll
        for (int d=0; d<EE; d++){
            float nx = snxt[w][d], rh = srh[w][d];
            at1 += nx*sW[d*192+128+e1] + rh*sU[d*192+128+e1];
            at2 += nx*sW[d*192+128+e2] + rh*sU[d*192+128+e2];
        }
        float ht1 = tanhf(at1), ht2 = tanhf(at2);
        g_h[(size_t)gn*EE+e1] = (1.0f-zg1)*h1 + zg1*ht1;
        g_h[(size_t)gn*EE+e2] = (1.0f-zg2)*h2 + zg2*ht2;
    }
}

// ---------------- decoder + dual heads (node scalars) ----------------
__global__ __launch_bounds__(256) void K_dec_dual(const float* __restrict__ dW0, const float* __restrict__ db0,
                                                  const float* __restrict__ dW1, const float* __restrict__ db1,
                                                  const float* __restrict__ uW0, const float* __restrict__ ub0,
                                                  const float* __restrict__ uW1, const float* __restrict__ ub1){
    __shared__ float sWd[EE*EE];
    __shared__ float sWu[EE*EE];
    __shared__ float shh[8][EE];
    int tid = threadIdx.x;
    for (int i=tid;i<EE*EE;i+=256){ sWd[i]=dW0[i]; sWu[i]=uW0[i]; }
    __syncthreads();
    int w = tid>>5, lane = tid&31;
    int e1 = lane, e2 = lane+32;
    #pragma unroll
    for (int rep=0; rep<2; rep++){
        int gn = blockIdx.x*16 + w + rep*8;
        float h1 = g_h[(size_t)gn*EE+e1], h2 = g_h[(size_t)gn*EE+e2];
        shh[w][e1]=h1; shh[w][e2]=h2;
        __syncwarp();
        float t1 = db0[e1], t2 = db0[e2];
        #pragma unroll
        for (int d=0; d<EE; d++){ float hv=shh[w][d]; t1 += hv*sWd[d*EE+e1]; t2 += hv*sWd[d*EE+e2]; }
        t1 = tanhf(t1); t2 = tanhf(t2);
        float p = warpSum(t1*dW1[e1] + t2*dW1[e2]);
        if (lane==0) g_nw[gn] = p + db1[0];
        float u1 = ub0[e1], u2 = ub0[e2];
        #pragma unroll
        for (int d=0; d<EE; d++){ float hv=shh[w][d]; u1 += hv*sWu[d*EE+e1]; u2 += hv*sWu[d*EE+e2]; }
        u1 = tanhf(u1); u2 = tanhf(u2);
        float q = warpSum(u1*uW1[e1] + u2*uW1[e2]);
        if (lane==0) g_dv[gn] = q + ub1[0];
        __syncwarp();
    }
}

// ---------------- global max of nw per batch ----------------
__global__ __launch_bounds__(256) void K_gmax(){
    int b = blockIdx.x;
    __shared__ float sr[8];
    float m = -1e30f;
    for (int n = threadIdx.x; n < NN; n += 256) m = fmaxf(m, g_nw[b*NN+n]);
    m = warpMax(m);
    if ((threadIdx.x&31)==0) sr[threadIdx.x>>5] = m;
    __syncthreads();
    if (threadIdx.x==0){
        float t = sr[0]; for(int i=1;i<8;i++) t=fmaxf(t,sr[i]);
        g_gmax[b] = t;
    }
}

// ---------------- softmax denominators + exp(nw) ----------------
__global__ __launch_bounds__(256) void K_prop(){
    int w = threadIdx.x>>5, lane = threadIdx.x&31;
    int gn = blockIdx.x*8 + w;
    int b = gn / NN;
    float gm = g_gmax[b];
    int deg = g_deg_adj[gn];
    const unsigned short* list = g_nbr_adj + (size_t)gn*MAXDEG_ADJ;
    float s = 0.f;
    for (int t=lane; t<deg; t+=32) s += __expf(g_nw[b*NN + list[t]] - gm);
    s = warpSum(s);
    if (lane==0){
        g_Z[gn] = (deg>0) ? s : 1.0f;
        g_enw[gn] = __expf(g_nw[gn] - gm);
    }
}

// ---------------- fused 10-iteration MCF, reverse-CSR gather (no atomics) ----
__global__ __launch_bounds__(1024) void K_flow(const float* __restrict__ demands){
    int b = blockIdx.x;
    __shared__ float us[NN];
    int n1 = threadIdx.x, n2 = threadIdx.x + 1024;
    int gn1 = b*NN+n1, gn2 = b*NN+n2;
    float invZ1 = 1.0f/g_Z[gn1], invZ2 = 1.0f/g_Z[gn2];
    float d1 = demands[gn1], d2 = demands[gn2];
    float e1 = g_enw[gn1],  e2 = g_enw[gn2];
    int rd1 = min(g_rdeg[gn1], MAXDEG_IN);
    int rd2 = min(g_rdeg[gn2], MAXDEG_IN);
    const unsigned short* l1 = g_rin + (size_t)gn1*MAXDEG_IN;
    const unsigned short* l2 = g_rin + (size_t)gn2*MAXDEG_IN;
    float s1 = 0.f, s2 = 0.f;
    for (int it=0; it<10; it++){
        us[n1] = s1*invZ1; us[n2] = s2*invZ2;
        __syncthreads();
        float a1 = 0.f, a2 = 0.f;
        for (int t=0; t<rd1; t++) a1 += us[l1[t]];
        for (int t=0; t<rd2; t++) a2 += us[l2[t]];
        s1 = fmaxf(fmaf(e1, a1, -d1), 0.f);
        s2 = fmaxf(fmaf(e2, a2, -d2), 0.f);
        __syncthreads();
    }
    g_s10[gn1] = s1;
    g_s10[gn2] = s2;
}

// ---------------- flow cost + dual iterations + final reduction ----------
__global__ __launch_bounds__(256) void K_final(const float* __restrict__ demands,
                                               float* __restrict__ out){
    int b = blockIdx.y;
    int tid = threadIdx.x, w = tid>>5, lane = tid&31;
    float acc = 0.f;
    for (int idx = w; idx < 64; idx += 8){
        int n = blockIdx.x*64 + idx;
        int gn = b*NN+n;
        int deg = g_deg_adj[gn];
        const unsigned short* list = g_nbr_adj + (size_t)gn*MAXDEG_ADJ;
        float si = g_s10[gn];
        float invZi = 1.0f/g_Z[gn];
        float dvi = g_dv[gn];
        float enwi = g_enw[gn];
        if (lane==0) acc += dvi * demands[gn];   // dual_demand (added to output)
        for (int t=lane; t<deg; t+=32){
            int j = list[t];
            int gj = b*NN+j;
            float f = g_enw[gj]*invZi*si;
            unsigned word = g_adjbit[(size_t)gj*(NN/32) + (n>>5)];
            float ft = 0.f;
            if ((word >> (n&31)) & 1u) ft = enwi * (g_s10[gj]/g_Z[gj]);
            float fp = f - fminf(f, ft);
            acc += fp*fp;
            float dd = dvi - g_dv[gj];
            float y = 0.f, m = 0.f;
            #pragma unroll
            for (int q=0; q<10; q++){
                float gg = 2.0f*y - dd;
                m = 0.9f*m + gg;
                y = fmaxf(y - 0.1f*m, 0.f);
            }
            acc -= (y*y - dd*y);   // minus dual edge term
        }
    }
    acc = warpSum(acc);
    __shared__ float sr[8];
    if (lane==0) sr[w] = acc;
    __syncthreads();
    if (tid==0){
        float t = 0.f; for (int i=0;i<8;i++) t += sr[i];
        atomicAdd(&out[b], t);
    }
}

// ---------------- launch ----------------
extern "C" void kernel_launch(void* const* d_in, const int* in_sizes, int n_in,
                              void* d_out, int out_size){
    const float* feat    = (const float*)d_in[0];
    const float* emb     = (const float*)d_in[1];
    const float* demands = (const float*)d_in[2];
    const float* neigh   = (const float*)d_in[4];
    const float* enc_W0  = (const float*)d_in[5];
    const float* enc_b0  = (const float*)d_in[6];
    const float* enc_W1  = (const float*)d_in[7];
    const float* enc_b1  = (const float*)d_in[8];
    const float* attn_W  = (const float*)d_in[9];
    const float* a_src   = (const float*)d_in[10];
    const float* a_dst   = (const float*)d_in[11];
    const float* nbr_q   = (const float*)d_in[12];
    const float* gru_W   = (const float*)d_in[13];
    const float* gru_U   = (const float*)d_in[14];
    const float* gru_b   = (const float*)d_in[15];
    const float* dec_W0  = (const float*)d_in[16];
    const float* dec_b0  = (const float*)d_in[17];
    const float* dec_W1  = (const float*)d_in[18];
    const float* dec_b1  = (const float*)d_in[19];
    const float* dual_W0 = (const float*)d_in[20];
    const float* dual_b0 = (const float*)d_in[21];
    const float* dual_W1 = (const float*)d_in[22];
    const float* dual_b1 = (const float*)d_in[23];
    float* out = (float*)d_out;

    cudaFuncSetAttribute(K_gru, cudaFuncAttributeMaxDynamicSharedMemorySize, 2*EE*192*4);

    K_zero<<<(BB*NN+255)/256,256>>>(out);
    K_enc<<<BB*NN/4,256>>>(emb, feat, enc_W0, enc_b0, enc_W1, enc_b1);
    K_build<<<KK*BB*NN/8,256>>>(neigh);
    for (int l=0;l<2;l++){
        K_z<<<dim3(BB*NN/64,HH),256>>>(attn_W, a_src, a_dst);
        K_zmean<<<HH*BB,256>>>();
        K_agg<<<dim3(BB*NN,KK),256>>>();
        K_gru<<<BB*NN/16,256, 2*EE*192*4>>>(nbr_q, gru_W, gru_U, gru_b);
    }
    K_dec_dual<<<BB*NN/16,256>>>(dec_W0,dec_b0,dec_W1,dec_b1,dual_W0,dual_b0,dual_W1,dual_b1);
    K_gmax<<<BB,256>>>();
    K_prop<<<BB*NN/8,256>>>();
    K_flow<<<BB,1024>>>(demands);
    K_final<<<dim3(NN/64,BB),256>>>(demands, out);
}

// round 4
// speedup vs baseline: 1.2198x; 1.0898x over previous
#include <cuda_runtime.h>
#include <cuda_bf16.h>
#include <math.h>

#define BB 2
#define NN 2048
#define EE 64
#define HH 2
#define KK 2
#define FIN 18
#define MAXDEG_ADJ 64
#define MAXDEG_A2 512
#define MAXDEG_IN 64
#define FULLMASK 0xffffffffu

// ---------------- device scratch (static, no allocation) ----------------
__device__ float g_h[BB*NN*EE];            // node hidden state
__device__ float g_zp[BB*NN*2*EE];         // packed per-node [head0 e0..63 | head1 e0..63]
__device__ float g_ssrc[HH*BB*NN];
__device__ float g_sdst[HH*BB*NN];
__device__ float g_hbar[BB*EE];            // sum of h over nodes (for zmean)
__device__ float g_zmean[HH*BB*EE];
__device__ float g_aggs[BB*NN*KK*EE];
__device__ unsigned short g_nbr_adj[BB*NN*MAXDEG_ADJ];
__device__ unsigned short g_nbr_a2[BB*NN*MAXDEG_A2];
__device__ unsigned short g_rin[BB*NN*MAXDEG_IN];
__device__ int g_deg_adj[BB*NN];
__device__ int g_deg_a2[BB*NN];
__device__ int g_rdeg[BB*NN];
__device__ unsigned g_adjbit[BB*NN*(NN/32)];
__device__ float g_nw[BB*NN];
__device__ float g_dv[BB*NN];
__device__ float g_enw[BB*NN];
__device__ float g_Z[BB*NN];
__device__ float g_s10[BB*NN];
__device__ float g_gmax[BB];

__device__ __forceinline__ float warpSum(float v){
    #pragma unroll
    for (int o=16;o;o>>=1) v += __shfl_xor_sync(FULLMASK, v, o);
    return v;
}
__device__ __forceinline__ float warpMax(float v){
    #pragma unroll
    for (int o=16;o;o>>=1) v = fmaxf(v, __shfl_xor_sync(FULLMASK, v, o));
    return v;
}
__device__ __forceinline__ float sigmoidf_(float x){ return 1.0f/(1.0f+__expf(-x)); }

// ---------------- zero output + counters ----------------
__global__ void K_zero(float* out){
    int idx = blockIdx.x*256 + threadIdx.x;
    if (idx < BB) out[idx] = 0.0f;
    if (idx < BB*EE) g_hbar[idx] = 0.0f;
    if (idx < BB*NN) g_rdeg[idx] = 0;
}

// ---------------- encoder: h = tanh(tanh(x@W0+b0)@W1+b1) ----------------
__global__ __launch_bounds__(256) void K_enc(const float* __restrict__ emb,
                                             const float* __restrict__ feat,
                                             const float* __restrict__ W0,
                                             const float* __restrict__ b0,
                                             const float* __restrict__ W1,
                                             const float* __restrict__ b1){
    __shared__ float sW0[FIN*EE];
    __shared__ float sW1[EE*EE];
    __shared__ float sx[4][FIN];
    __shared__ float st[4][EE];
    int tid = threadIdx.x;
    for (int i = tid; i < FIN*EE; i += 256) sW0[i] = W0[i];
    for (int i = tid; i < EE*EE;  i += 256) sW1[i] = W1[i];
    int g = tid >> 6, e = tid & 63;
    int gn = blockIdx.x*4 + g;
    if (e < 16)       sx[g][e]   = emb[gn*16 + e];
    else if (e < 18)  sx[g][e]   = feat[gn*2 + (e-16)];
    __syncthreads();
    float acc = b0[e];
    #pragma unroll
    for (int d=0; d<FIN; d++) acc += sx[g][d]*sW0[d*EE+e];
    st[g][e] = tanhf(acc);
    __syncthreads();
    float acc2 = b1[e];
    #pragma unroll
    for (int d=0; d<EE; d++) acc2 += st[g][d]*sW1[d*EE+e];
    g_h[gn*EE+e] = tanhf(acc2);
}

// ---------------- CSR + bitset + reverse-CSR build ----------------
__global__ __launch_bounds__(256) void K_build(const float* __restrict__ neigh){
    int lane = threadIdx.x & 31;
    int row = blockIdx.x*8 + (threadIdx.x >> 5);   // 0 .. KK*BB*NN-1
    int k  = row / (BB*NN);
    int bn = row % (BB*NN);
    int b_ = bn / NN, i_ = bn % NN;
    const float* src = neigh + (size_t)row * NN;
    unsigned short* dst = (k==0) ? (g_nbr_adj + (size_t)bn*MAXDEG_ADJ)
                                 : (g_nbr_a2  + (size_t)bn*MAXDEG_A2);
    int cap = (k==0) ? MAXDEG_ADJ : MAXDEG_A2;
    int deg = 0;
    #pragma unroll 4
    for (int c=0; c<NN/32; c++){
        int j = c*32 + lane;
        float v = src[j];
        bool p = v > 0.0f;
        unsigned bal = __ballot_sync(FULLMASK, p);
        if (k==0 && lane==0) g_adjbit[(size_t)bn*(NN/32) + c] = bal;
        int pre = __popc(bal & ((1u<<lane)-1u));
        if (p){
            int pos = deg + pre;
            if (pos < cap) dst[pos] = (unsigned short)j;
            if (k==0){
                int rp = atomicAdd(&g_rdeg[b_*NN + j], 1);
                if (rp < MAXDEG_IN) g_rin[(size_t)(b_*NN+j)*MAXDEG_IN + rp] = (unsigned short)i_;
            }
        }
        deg += __popc(bal);
    }
    if (lane==0){
        if (deg > cap) deg = cap;
        if (k==0) g_deg_adj[bn] = deg; else g_deg_a2[bn] = deg;
    }
}

// ---------------- mean of h over nodes (partial, atomics) ----------------
__global__ __launch_bounds__(256) void K_hmean(){
    // grid: BB*16 blocks, 128 nodes each
    int b = blockIdx.x >> 4;
    int seg = blockIdx.x & 15;
    int part = threadIdx.x >> 6, e = threadIdx.x & 63;
    __shared__ float sp[4][EE];
    float s = 0.f;
    int n0 = seg*128 + part;
    #pragma unroll 4
    for (int n = n0; n < seg*128 + 128; n += 4)
        s += g_h[(size_t)(b*NN+n)*EE + e];
    sp[part][e] = s;
    __syncthreads();
    if (threadIdx.x < EE){
        float t = sp[0][threadIdx.x]+sp[1][threadIdx.x]+sp[2][threadIdx.x]+sp[3][threadIdx.x];
        atomicAdd(&g_hbar[b*EE + threadIdx.x], t);
    }
}

// ---------------- zmean = (hbar/N) @ W  (1 block), then clear hbar --------
__global__ __launch_bounds__(128) void K_zm2(const float* __restrict__ attn_W){
    int h = threadIdx.x >> 6, e = threadIdx.x & 63;
    const float* W = attn_W + h*EE*EE;
    float zm[BB];
    #pragma unroll
    for (int b=0; b<BB; b++){
        float acc = 0.f;
        #pragma unroll 4
        for (int d=0; d<EE; d++) acc += g_hbar[b*EE+d]*W[d*EE+e];
        zm[b] = acc * (1.0f/(float)NN);
    }
    __syncthreads();
    #pragma unroll
    for (int b=0; b<BB; b++) g_zmean[(h*BB+b)*EE+e] = zm[b];
    if (threadIdx.x < BB*EE) g_hbar[threadIdx.x] = 0.0f;
}

// ---------------- per-head projection z + attention logits ----------------
// 32 nodes per block, 256 threads; thread computes 4 e's x 2 nodes
__global__ __launch_bounds__(256) void K_z(const float* __restrict__ attn_W,
                                           const float* __restrict__ a_src,
                                           const float* __restrict__ a_dst){
    int h = blockIdx.y;
    __shared__ __align__(16) float sW[EE*EE];     // [d][e]
    __shared__ __align__(16) float sh[32][68];    // padded: conflict-free
    int tid = threadIdx.x;
    const float* W = attn_W + h*EE*EE;
    for (int i=tid;i<EE*EE;i+=256) sW[i] = W[i];
    int gn0 = blockIdx.x*32;
    for (int i=tid;i<32*EE;i+=256) sh[i>>6][i&63] = g_h[(size_t)gn0*EE + i];
    __syncthreads();
    int eg = tid & 15;          // e-group: elements eg*4..eg*4+3
    int ng = tid >> 4;          // node group: nodes ng*2, ng*2+1
    int n0 = ng*2, n1 = ng*2+1;
    float4 acc0 = {0,0,0,0}, acc1 = {0,0,0,0};
    const float4* sW4 = (const float4*)sW;
    #pragma unroll 4
    for (int d=0; d<EE; d++){
        float4 wv = sW4[d*16 + eg];
        float h0 = sh[n0][d];
        float h1 = sh[n1][d];
        acc0.x += h0*wv.x; acc0.y += h0*wv.y; acc0.z += h0*wv.z; acc0.w += h0*wv.w;
        acc1.x += h1*wv.x; acc1.y += h1*wv.y; acc1.z += h1*wv.z; acc1.w += h1*wv.w;
    }
    *(float4*)(g_zp + ((size_t)(gn0+n0))*2*EE + h*EE + eg*4) = acc0;
    *(float4*)(g_zp + ((size_t)(gn0+n1))*2*EE + h*EE + eg*4) = acc1;
    // fused s_src/s_dst: each node's 64 e live in 16 consecutive lanes
    const float4* as4 = (const float4*)(a_src + h*EE);
    const float4* ad4 = (const float4*)(a_dst + h*EE);
    float4 as = as4[eg], ad = ad4[eg];
    float p0 = acc0.x*as.x + acc0.y*as.y + acc0.z*as.z + acc0.w*as.w;
    float q0 = acc0.x*ad.x + acc0.y*ad.y + acc0.z*ad.z + acc0.w*ad.w;
    float p1 = acc1.x*as.x + acc1.y*as.y + acc1.z*as.z + acc1.w*as.w;
    float q1 = acc1.x*ad.x + acc1.y*ad.y + acc1.z*ad.z + acc1.w*ad.w;
    #pragma unroll
    for (int o=8;o;o>>=1){
        p0 += __shfl_down_sync(FULLMASK, p0, o, 16);
        q0 += __shfl_down_sync(FULLMASK, q0, o, 16);
        p1 += __shfl_down_sync(FULLMASK, p1, o, 16);
        q1 += __shfl_down_sync(FULLMASK, q1, o, 16);
    }
    if (eg == 0){
        g_ssrc[h*BB*NN + gn0 + n0] = p0;
        g_sdst[h*BB*NN + gn0 + n0] = q0;
        g_ssrc[h*BB*NN + gn0 + n1] = p1;
        g_sdst[h*BB*NN + gn0 + n1] = q1;
    }
}

// ---------------- neighborhood attention aggregation (fused, unrolled) ----
__global__ __launch_bounds__(256) void K_agg(){
    int bn = blockIdx.x;         // b*NN+n
    int k  = blockIdx.y;
    int b  = bn / NN;
    int tid = threadIdx.x, w = tid>>5, lane = tid&31;

    __shared__ float sacc[8][128];
    __shared__ float sw0[8], sw1[8];
    __shared__ unsigned short sj[8][32];
    __shared__ float swt[8][2][32];

    int deg = (k==0) ? g_deg_adj[bn] : g_deg_a2[bn];
    const unsigned short* list = (k==0) ? (g_nbr_adj + (size_t)bn*MAXDEG_ADJ)
                                        : (g_nbr_a2  + (size_t)bn*MAXDEG_A2);
    if (deg == 0){
        if (tid < EE){
            float v = 0.5f*(g_zmean[(0*BB+b)*EE+tid] + g_zmean[(1*BB+b)*EE+tid]);
            g_aggs[((size_t)bn*KK + k)*EE + tid] = tanhf(v);
        }
        return;
    }
    float ssrc0 = g_ssrc[0*BB*NN + bn];
    float ssrc1 = g_ssrc[1*BB*NN + bn];
    const float* sd0 = g_sdst + 0*BB*NN + b*NN;
    const float* sd1 = g_sdst + 1*BB*NN + b*NN;
    const float* zb  = g_zp + (size_t)b*NN*2*EE;

    float a0=0.f, a1=0.f, a2=0.f, a3=0.f;
    float s0=0.f, s1=0.f;
    const float* wrow = swt[w][lane>>4];   // lane<16 -> head0 weights
    int lane4 = lane*4;
    for (int base = w*32; base < deg; base += 256){
        int cnt = deg - base; if (cnt > 32) cnt = 32;
        int jl = 0; float w0l = 0.f, w1l = 0.f;
        if (lane < cnt){
            jl = list[base + lane];
            w0l = __expf(tanhf(ssrc0 + sd0[jl]));
            w1l = __expf(tanhf(ssrc1 + sd1[jl]));
        }
        s0 += w0l; s1 += w1l;
        sj[w][lane] = (unsigned short)jl;
        swt[w][0][lane] = w0l;
        swt[w][1][lane] = w1l;
        __syncwarp();
        if (cnt == 32){
            #pragma unroll 8
            for (int i=0;i<32;i++){
                int j = sj[w][i]; float wt = wrow[i];
                float4 v = *(const float4*)(zb + (size_t)j*2*EE + lane4);
                a0 += wt*v.x; a1 += wt*v.y; a2 += wt*v.z; a3 += wt*v.w;
            }
        } else {
            for (int i=0;i<cnt;i++){
                int j = sj[w][i]; float wt = wrow[i];
                float4 v = *(const float4*)(zb + (size_t)j*2*EE + lane4);
                a0 += wt*v.x; a1 += wt*v.y; a2 += wt*v.z; a3 += wt*v.w;
            }
        }
        __syncwarp();
    }
    s0 = warpSum(s0); s1 = warpSum(s1);
    if (lane==0){ sw0[w]=s0; sw1[w]=s1; }
    sacc[w][lane4+0]=a0; sacc[w][lane4+1]=a1;
    sacc[w][lane4+2]=a2; sacc[w][lane4+3]=a3;
    __syncthreads();
    if (tid < EE){
        float r0=0.f, r1=0.f, S0=0.f, S1=0.f;
        #pragma unroll
        for (int ww=0; ww<8; ww++){
            r0 += sacc[ww][tid];
            r1 += sacc[ww][64+tid];
            S0 += sw0[ww]; S1 += sw1[ww];
        }
        float v = 0.5f*(r0/S0 + r1/S1);
        g_aggs[((size_t)bn*KK + k)*EE + tid] = tanhf(v);
    }
}

// ---------------- combine neighborhoods + GRU update (fused) -------------
__global__ __launch_bounds__(256) void K_gru(const float* __restrict__ nbr_q,
                                             const float* __restrict__ gru_W,
                                             const float* __restrict__ gru_U,
                                             const float* __restrict__ gru_b){
    extern __shared__ float dyn[];
    float* sW = dyn;              // 64*192
    float* sU = dyn + EE*192;     // 64*192
    __shared__ float snxt[8][EE];
    __shared__ float shh [8][EE];
    __shared__ float srh [8][EE];
    int tid = threadIdx.x;
    for (int i=tid;i<EE*192;i+=256){ sW[i]=gru_W[i]; sU[i]=gru_U[i]; }
    __syncthreads();
    int w = tid>>5, lane = tid&31;
    int e1 = lane, e2 = lane+32;
    #pragma unroll
    for (int rep=0; rep<2; rep++){
        int gn = blockIdx.x*16 + w + rep*8;
        const float* ag = g_aggs + (size_t)gn*KK*EE;
        float a0_1 = ag[e1],      a0_2 = ag[e2];
        float a1_1 = ag[EE+e1],   a1_2 = ag[EE+e2];
        float d0 = warpSum(a0_1*nbr_q[e1] + a0_2*nbr_q[e2]);
        float d1 = warpSum(a1_1*nbr_q[e1] + a1_2*nbr_q[e2]);
        float t0 = tanhf(d0), t1 = tanhf(d1);
        float mx = fmaxf(t0,t1);
        float ex0 = __expf(t0-mx), ex1 = __expf(t1-mx);
        float inv = 1.0f/(ex0+ex1);
        float c0 = ex0*inv, c1 = ex1*inv;
        float nx1 = c0*a0_1 + c1*a1_1;
        float nx2 = c0*a0_2 + c1*a1_2;
        float h1 = g_h[(size_t)gn*EE+e1], h2 = g_h[(size_t)gn*EE+e2];
        snxt[w][e1]=nx1; snxt[w][e2]=nx2;
        shh [w][e1]=h1;  shh [w][e2]=h2;
        __syncwarp();
        float az1 = gru_b[e1],    az2 = gru_b[e2];
        float ar1 = gru_b[64+e1], ar2 = gru_b[64+e2];
        #pragma unroll
        for (int d=0; d<EE; d++){
            float nx = snxt[w][d], hv = shh[w][d];
            az1 += nx*sW[d*192+e1]    + hv*sU[d*192+e1];
            az2 += nx*sW[d*192+e2]    + hv*sU[d*192+e2];
            ar1 += nx*sW[d*192+64+e1] + hv*sU[d*192+64+e1];
            ar2 += nx*sW[d*192+64+e2] + hv*sU[d*192+64+e2];
        }
        float zg1 = sigmoidf_(az1), zg2 = sigmoidf_(az2);
        float r1  = sigmoidf_(ar1), r2  = sigmoidf_(ar2);
        srh[w][e1] = r1*h1; srh[w][e2] = r2*h2;
        __syncwarp();
        float at1 = gru_b[128+e1], at2 = gru_b[128+e2];
        #pragma unroll
        for (int d=0; d<EE; d++){
            float nx = snxt[w][d], rh = srh[w][d];
            at1 += nx*sW[d*192+128+e1] + rh*sU[d*192+128+e1];
            at2 += nx*sW[d*192+128+e2] + rh*sU[d*192+128+e2];
        }
        float ht1 = tanhf(at1), ht2 = tanhf(at2);
        g_h[(size_t)gn*EE+e1] = (1.0f-zg1)*h1 + zg1*ht1;
        g_h[(size_t)gn*EE+e2] = (1.0f-zg2)*h2 + zg2*ht2;
    }
}

// ---------------- decoder + dual heads (node scalars) ----------------
__global__ __launch_bounds__(256) void K_dec_dual(const float* __restrict__ dW0, const float* __restrict__ db0,
                                                  const float* __restrict__ dW1, const float* __restrict__ db1,
                                                  const float* __restrict__ uW0, const float* __restrict__ ub0,
                                                  const float* __restrict__ uW1, const float* __restrict__ ub1){
    __shared__ float sWd[EE*EE];
    __shared__ float sWu[EE*EE];
    __shared__ float shh[8][EE];
    int tid = threadIdx.x;
    for (int i=tid;i<EE*EE;i+=256){ sWd[i]=dW0[i]; sWu[i]=uW0[i]; }
    __syncthreads();
    int w = tid>>5, lane = tid&31;
    int e1 = lane, e2 = lane+32;
    #pragma unroll
    for (int rep=0; rep<2; rep++){
        int gn = blockIdx.x*16 + w + rep*8;
        float h1 = g_h[(size_t)gn*EE+e1], h2 = g_h[(size_t)gn*EE+e2];
        shh[w][e1]=h1; shh[w][e2]=h2;
        __syncwarp();
        float t1 = db0[e1], t2 = db0[e2];
        #pragma unroll
        for (int d=0; d<EE; d++){ float hv=shh[w][d]; t1 += hv*sWd[d*EE+e1]; t2 += hv*sWd[d*EE+e2]; }
        t1 = tanhf(t1); t2 = tanhf(t2);
        float p = warpSum(t1*dW1[e1] + t2*dW1[e2]);
        if (lane==0) g_nw[gn] = p + db1[0];
        float u1 = ub0[e1], u2 = ub0[e2];
        #pragma unroll
        for (int d=0; d<EE; d++){ float hv=shh[w][d]; u1 += hv*sWu[d*EE+e1]; u2 += hv*sWu[d*EE+e2]; }
        u1 = tanhf(u1); u2 = tanhf(u2);
        float q = warpSum(u1*uW1[e1] + u2*uW1[e2]);
        if (lane==0) g_dv[gn] = q + ub1[0];
        __syncwarp();
    }
}

// ---------------- global max of nw per batch ----------------
__global__ __launch_bounds__(256) void K_gmax(){
    int b = blockIdx.x;
    __shared__ float sr[8];
    float m = -1e30f;
    for (int n = threadIdx.x; n < NN; n += 256) m = fmaxf(m, g_nw[b*NN+n]);
    m = warpMax(m);
    if ((threadIdx.x&31)==0) sr[threadIdx.x>>5] = m;
    __syncthreads();
    if (threadIdx.x==0){
        float t = sr[0]; for(int i=1;i<8;i++) t=fmaxf(t,sr[i]);
        g_gmax[b] = t;
    }
}

// ---------------- softmax denominators + exp(nw) ----------------
__global__ __launch_bounds__(256) void K_prop(){
    int w = threadIdx.x>>5, lane = threadIdx.x&31;
    int gn = blockIdx.x*8 + w;
    int b = gn / NN;
    float gm = g_gmax[b];
    int deg = g_deg_adj[gn];
    const unsigned short* list = g_nbr_adj + (size_t)gn*MAXDEG_ADJ;
    float s = 0.f;
    for (int t=lane; t<deg; t+=32) s += __expf(g_nw[b*NN + list[t]] - gm);
    s = warpSum(s);
    if (lane==0){
        g_Z[gn] = (deg>0) ? s : 1.0f;
        g_enw[gn] = __expf(g_nw[gn] - gm);
    }
}

// ---------------- fused 10-iteration MCF, reverse-CSR gather (no atomics) ----
__global__ __launch_bounds__(1024) void K_flow(const float* __restrict__ demands){
    int b = blockIdx.x;
    __shared__ float us[NN];
    int n1 = threadIdx.x, n2 = threadIdx.x + 1024;
    int gn1 = b*NN+n1, gn2 = b*NN+n2;
    float invZ1 = 1.0f/g_Z[gn1], invZ2 = 1.0f/g_Z[gn2];
    float d1 = demands[gn1], d2 = demands[gn2];
    float e1 = g_enw[gn1],  e2 = g_enw[gn2];
    int rd1 = min(g_rdeg[gn1], MAXDEG_IN);
    int rd2 = min(g_rdeg[gn2], MAXDEG_IN);
    const unsigned short* l1 = g_rin + (size_t)gn1*MAXDEG_IN;
    const unsigned short* l2 = g_rin + (size_t)gn2*MAXDEG_IN;
    float s1 = 0.f, s2 = 0.f;
    for (int it=0; it<10; it++){
        us[n1] = s1*invZ1; us[n2] = s2*invZ2;
        __syncthreads();
        float a1 = 0.f, a2 = 0.f;
        for (int t=0; t<rd1; t++) a1 += us[l1[t]];
        for (int t=0; t<rd2; t++) a2 += us[l2[t]];
        s1 = fmaxf(fmaf(e1, a1, -d1), 0.f);
        s2 = fmaxf(fmaf(e2, a2, -d2), 0.f);
        __syncthreads();
    }
    g_s10[gn1] = s1;
    g_s10[gn2] = s2;
}

// ---------------- flow cost + dual iterations + final reduction ----------
__global__ __launch_bounds__(256) void K_final(const float* __restrict__ demands,
                                               float* __restrict__ out){
    int b = blockIdx.y;
    int tid = threadIdx.x, w = tid>>5, lane = tid&31;
    float acc = 0.f;
    for (int idx = w; idx < 64; idx += 8){
        int n = blockIdx.x*64 + idx;
        int gn = b*NN+n;
        int deg = g_deg_adj[gn];
        const unsigned short* list = g_nbr_adj + (size_t)gn*MAXDEG_ADJ;
        float si = g_s10[gn];
        float invZi = 1.0f/g_Z[gn];
        float dvi = g_dv[gn];
        float enwi = g_enw[gn];
        if (lane==0) acc += dvi * demands[gn];   // dual_demand (added to output)
        for (int t=lane; t<deg; t+=32){
            int j = list[t];
            int gj = b*NN+j;
            float f = g_enw[gj]*invZi*si;
            unsigned word = g_adjbit[(size_t)gj*(NN/32) + (n>>5)];
            float ft = 0.f;
            if ((word >> (n&31)) & 1u) ft = enwi * (g_s10[gj]/g_Z[gj]);
            float fp = f - fminf(f, ft);
            acc += fp*fp;
            float dd = dvi - g_dv[gj];
            float y = 0.f, m = 0.f;
            #pragma unroll
            for (int q=0; q<10; q++){
                float gg = 2.0f*y - dd;
                m = 0.9f*m + gg;
                y = fmaxf(y - 0.1f*m, 0.f);
            }
            acc -= (y*y - dd*y);   // minus dual edge term
        }
    }
    acc = warpSum(acc);
    __shared__ float sr[8];
    if (lane==0) sr[w] = acc;
    __syncthreads();
    if (tid==0){
        float t = 0.f; for (int i=0;i<8;i++) t += sr[i];
        atomicAdd(&out[b], t);
    }
}

// ---------------- launch ----------------
extern "C" void kernel_launch(void* const* d_in, const int* in_sizes, int n_in,
                              void* d_out, int out_size){
    const float* feat    = (const float*)d_in[0];
    const float* emb     = (const float*)d_in[1];
    const float* demands = (const float*)d_in[2];
    const float* neigh   = (const float*)d_in[4];
    const float* enc_W0  = (const float*)d_in[5];
    const float* enc_b0  = (const float*)d_in[6];
    const float* enc_W1  = (const float*)d_in[7];
    const float* enc_b1  = (const float*)d_in[8];
    const float* attn_W  = (const float*)d_in[9];
    const float* a_src   = (const float*)d_in[10];
    const float* a_dst   = (const float*)d_in[11];
    const float* nbr_q   = (const float*)d_in[12];
    const float* gru_W   = (const float*)d_in[13];
    const float* gru_U   = (const float*)d_in[14];
    const float* gru_b   = (const float*)d_in[15];
    const float* dec_W0  = (const float*)d_in[16];
    const float* dec_b0  = (const float*)d_in[17];
    const float* dec_W1  = (const float*)d_in[18];
    const float* dec_b1  = (const float*)d_in[19];
    const float* dual_W0 = (const float*)d_in[20];
    const float* dual_b0 = (const float*)d_in[21];
    const float* dual_W1 = (const float*)d_in[22];
    const float* dual_b1 = (const float*)d_in[23];
    float* out = (float*)d_out;

    cudaFuncSetAttribute(K_gru, cudaFuncAttributeMaxDynamicSharedMemorySize, 2*EE*192*4);

    K_zero<<<(BB*NN+255)/256,256>>>(out);
    K_enc<<<BB*NN/4,256>>>(emb, feat, enc_W0, enc_b0, enc_W1, enc_b1);
    K_build<<<KK*BB*NN/8,256>>>(neigh);
    for (int l=0;l<2;l++){
        K_hmean<<<BB*16,256>>>();
        K_zm2<<<1,128>>>(attn_W);
        K_z<<<dim3(BB*NN/32,HH),256>>>(attn_W, a_src, a_dst);
        K_agg<<<dim3(BB*NN,KK),256>>>();
        K_gru<<<BB*NN/16,256, 2*EE*192*4>>>(nbr_q, gru_W, gru_U, gru_b);
    }
    K_dec_dual<<<BB*NN/16,256>>>(dec_W0,dec_b0,dec_W1,dec_b1,dual_W0,dual_b0,dual_W1,dual_b1);
    K_gmax<<<BB,256>>>();
    K_prop<<<BB*NN/8,256>>>();
    K_flow<<<BB,1024>>>(demands);
    K_final<<<dim3(NN/64,BB),256>>>(demands, out);
}